// round 17
// baseline (speedup 1.0000x reference)
#include <cuda_runtime.h>
#include <cuda_fp16.h>
#include <math_constants.h>
#include <cstdint>

// Problem constants
#define S_LEN   4096
#define D_MODEL 512
#define H_NUM   8
#define HD      64
#define LDQKV   1536      // 3*D_MODEL

// Q pre-scale: 1/sqrt(64) * log2(e)  (softmax runs in exp2 domain)
#define Q_PRESCALE 0.18033688011112042f

// Scratch (no cudaMalloc allowed) -- all fp16
__device__ __half g_qkv[S_LEN * LDQKV];       // [4096,1536] Q|K|V (fp16, Q pre-scaled)
__device__ __half g_attn[S_LEN * D_MODEL];    // [4096,512]  attention out (fp16)
__device__ __half g_qr [S_LEN * D_MODEL];     // query, fp16
__device__ __half g_wi [3 * D_MODEL * D_MODEL]; // in_proj_weight, fp16
__device__ __half g_wo [D_MODEL * D_MODEL];   // out_proj_weight, fp16

// ---------------------------------------------------------------------------
// Helpers
// ---------------------------------------------------------------------------
__device__ __forceinline__ float ex2f(float x) {
    float y;
    asm("ex2.approx.ftz.f32 %0, %1;" : "=f"(y) : "f"(x));
    return y;
}

// m16n8k16 fp16 mma, fp32 accumulate
__device__ __forceinline__ void mma_f16(float d[4], const uint32_t a[4],
                                        const uint32_t b[2], const float c[4]) {
    asm volatile(
        "mma.sync.aligned.m16n8k16.row.col.f32.f16.f16.f32 "
        "{%0,%1,%2,%3}, {%4,%5,%6,%7}, {%8,%9}, {%10,%11,%12,%13};"
        : "=f"(d[0]), "=f"(d[1]), "=f"(d[2]), "=f"(d[3])
        : "r"(a[0]), "r"(a[1]), "r"(a[2]), "r"(a[3]),
          "r"(b[0]), "r"(b[1]),
          "f"(c[0]), "f"(c[1]), "f"(c[2]), "f"(c[3]));
}

// ldmatrix x4, non-transposed (b16): fragment = lane l -> row l>>2, cols 2(l&3)
__device__ __forceinline__ void ldsm_x4(uint32_t& r0, uint32_t& r1,
                                        uint32_t& r2, uint32_t& r3, uint32_t addr) {
    asm volatile("ldmatrix.sync.aligned.m8n8.x4.shared.b16 {%0,%1,%2,%3}, [%4];"
                 : "=r"(r0), "=r"(r1), "=r"(r2), "=r"(r3) : "r"(addr));
}

// ldmatrix x4 transposed (b16): B-fragment loader for row-major [k][n] V
__device__ __forceinline__ void ldsm_x4_t(uint32_t& r0, uint32_t& r1,
                                          uint32_t& r2, uint32_t& r3, uint32_t addr) {
    asm volatile("ldmatrix.sync.aligned.m8n8.x4.trans.shared.b16 {%0,%1,%2,%3}, [%4];"
                 : "=r"(r0), "=r"(r1), "=r"(r2), "=r"(r3) : "r"(addr));
}

__device__ __forceinline__ uint32_t smem_u32(const void* p) {
    uint32_t a;
    asm("{ .reg .u64 t; cvta.to.shared.u64 t, %1; cvt.u32.u64 %0, t; }"
        : "=r"(a) : "l"(p));
    return a;
}

// cp.async.ca: 16B gmem->smem, L1-preserving
__device__ __forceinline__ void cp_async16(uint32_t dst, const void* src) {
    asm volatile("cp.async.ca.shared.global [%0], [%1], 16;"
                 :: "r"(dst), "l"(src));
}
#define CP_COMMIT()  asm volatile("cp.async.commit_group;")
#define CP_WAIT0()   asm volatile("cp.async.wait_group 0;")
#define CP_WAIT1()   asm volatile("cp.async.wait_group 1;")

// ---------------------------------------------------------------------------
// Elementwise fp32 -> fp16 rounding pass (src -> dst), 4 elems/thread.
// ---------------------------------------------------------------------------
__global__ void round_f16_kernel(const float* __restrict__ src,
                                 __half* __restrict__ dst, int n4) {
    int i = blockIdx.x * blockDim.x + threadIdx.x;
    if (i < n4) {
        float4 v = *(const float4*)(src + 4 * i);
        __half2 h01 = __floats2half2_rn(v.x, v.y);
        __half2 h23 = __floats2half2_rn(v.z, v.w);
        *(__half2*)(dst + 4 * i)     = h01;
        *(__half2*)(dst + 4 * i + 2) = h23;
    }
}

// ---------------------------------------------------------------------------
// fp16 tensor-core GEMM (m16n8k16): C[M,N] = A[M,K] @ B[N,K]^T + bias[N]
// 128x128 CTA tile, 128 threads = 2x2 warp grid of 64x64 warp tiles.
// NOW 3-STAGE cp.async pipeline: wait_group 1 in steady state (tile t's
// data guaranteed by group-FIFO order), wait_group 0 on the final tile.
// The loop-top barrier separates tile t-1's smem reads from tile t+2's
// cp.async writes into the same mod-3 buffer.
// ---------------------------------------------------------------------------
#define LDH 40
#define GEMM_SMEM (3 * 2 * 128 * LDH * 2)   // 61440 bytes (3-stage)

__global__ void __launch_bounds__(128, 2) gemm_f16_bias(
    const __half* __restrict__ A, const __half* __restrict__ B,
    const float* __restrict__ bias, void* __restrict__ Cv,
    int M, int N, int K, int qkv_round)
{
    extern __shared__ __half smh[];
    __half* As[3] = { smh, smh + 2 * 128 * LDH, smh + 4 * 128 * LDH };
    __half* Bs[3] = { smh + 128 * LDH, smh + 3 * 128 * LDH, smh + 5 * 128 * LDH };

    const int tid  = threadIdx.x;
    const int lane = tid & 31;
    const int wid  = tid >> 5;          // 0..3
    const int qc   = lane & 3;
    const int qg   = lane >> 2;
    const int wm   = (wid & 1) * 64;    // 2x2 warp grid, 64x64 warp tiles
    const int wn   = (wid >> 1) * 64;
    const int m0   = blockIdx.y * 128;
    const int n0   = blockIdx.x * 128;

    uint32_t aS[3][4], bS[3][4];
#pragma unroll
    for (int i = 0; i < 4; i++) {
        int id  = tid + i * 128;
        int row = id >> 2;
        int c8  = (id & 3) * 8;
#pragma unroll
        for (int s = 0; s < 3; s++) {
            aS[s][i] = smem_u32(As[s] + row * LDH + c8);
            bS[s][i] = smem_u32(Bs[s] + row * LDH + c8);
        }
    }

    float acc[4][8][4];
#pragma unroll
    for (int mf = 0; mf < 4; mf++)
#pragma unroll
        for (int nf = 0; nf < 8; nf++)
#pragma unroll
            for (int j = 0; j < 4; j++) acc[mf][nf][j] = 0.0f;

    const int nt = K / 32;   // >= 2 for all our shapes (K=512 -> 16)

    // prologue: stage tiles 0 and 1 as separate groups
#pragma unroll
    for (int s = 0; s < 2; s++) {
        int k0 = s * 32;
#pragma unroll
        for (int i = 0; i < 4; i++) {
            int id  = tid + i * 128;
            int row = id >> 2;
            int c8  = (id & 3) * 8;
            cp_async16(aS[s][i], A + (size_t)(m0 + row) * K + k0 + c8);
            cp_async16(bS[s][i], B + (size_t)(n0 + row) * K + k0 + c8);
        }
        CP_COMMIT();
    }

    for (int t = 0; t < nt; t++) {
        const int cur = t % 3;
        if (t + 1 < nt) { CP_WAIT1(); } else { CP_WAIT0(); }
        __syncthreads();

        if (t + 2 < nt) {
            const int nxt = (t + 2) % 3;
            int k0 = (t + 2) * 32;
#pragma unroll
            for (int i = 0; i < 4; i++) {
                int id  = tid + i * 128;
                int row = id >> 2;
                int c8  = (id & 3) * 8;
                cp_async16(aS[nxt][i], A + (size_t)(m0 + row) * K + k0 + c8);
                cp_async16(bS[nxt][i], B + (size_t)(n0 + row) * K + k0 + c8);
            }
            CP_COMMIT();
        }

        const __half* as = As[cur];
        const __half* bs = Bs[cur];
#pragma unroll
        for (int kc = 0; kc < 2; kc++) {
            uint32_t bfr[8][2];
#pragma unroll
            for (int nf = 0; nf < 8; nf++) {
                const __half* bp = bs + (wn + nf * 8 + qg) * LDH + kc * 16 + 2 * qc;
                bfr[nf][0] = *(const uint32_t*)(bp);
                bfr[nf][1] = *(const uint32_t*)(bp + 8);
            }
#pragma unroll
            for (int mf = 0; mf < 4; mf++) {
                const __half* ap = as + (wm + mf * 16 + qg) * LDH + kc * 16 + 2 * qc;
                uint32_t afr[4];
                afr[0] = *(const uint32_t*)(ap);
                afr[1] = *(const uint32_t*)(ap + 8 * LDH);
                afr[2] = *(const uint32_t*)(ap + 8);
                afr[3] = *(const uint32_t*)(ap + 8 * LDH + 8);
#pragma unroll
                for (int nf = 0; nf < 8; nf++)
                    mma_f16(acc[mf][nf], afr, bfr[nf], acc[mf][nf]);
            }
        }
    }

#pragma unroll
    for (int mf = 0; mf < 4; mf++) {
        int row0 = m0 + wm + mf * 16 + qg;
#pragma unroll
        for (int nf = 0; nf < 8; nf++) {
            int col = n0 + wn + nf * 8 + 2 * qc;
            float b0 = bias[col], b1 = bias[col + 1];
            float v00 = acc[mf][nf][0] + b0, v01 = acc[mf][nf][1] + b1;
            float v10 = acc[mf][nf][2] + b0, v11 = acc[mf][nf][3] + b1;
            if (qkv_round) {
                float sc = (col < D_MODEL) ? Q_PRESCALE : 1.0f;  // scale Q only
                __half* C = (__half*)Cv;
                *(__half2*)(C + (size_t)row0 * N + col) =
                    __floats2half2_rn(v00 * sc, v01 * sc);
                *(__half2*)(C + (size_t)(row0 + 8) * N + col) =
                    __floats2half2_rn(v10 * sc, v11 * sc);
            } else {
                float* C = (float*)Cv;
                *(float2*)(C + (size_t)row0 * N + col)       = make_float2(v00, v01);
                *(float2*)(C + (size_t)(row0 + 8) * N + col) = make_float2(v10, v11);
            }
        }
    }
}

// ---------------------------------------------------------------------------
// Flash attention, fp16 mma (m16n8k16), Br=128 / Bc=64 / Hd=64, 4 warps,
// 32 q-rows/warp. R15 winner with fragment loads upgraded to ldmatrix:
//  - V B-frags: ldmatrix.x4.trans (verified R15)
//  - K B-frags: ldmatrix.x4 non-trans (canonical b16 fragment layout)
//  - P A-frags: ldmatrix.x4 non-trans
// 96 scalar LDS -> 24 LDSM per warp-tile; staging/softmax unchanged.
// ---------------------------------------------------------------------------
#define LDH_F 72
#define FLASH_SMEM ((64 * LDH_F + 64 * LDH_F + 128 * LDH_F) * 2)   // 36864 B

__global__ void __launch_bounds__(128, 2) flash_mma_kernel(
    const __half* __restrict__ qkv, __half* __restrict__ attn_out)
{
    extern __shared__ __half smh[];
    __half* Ks = smh;                            // [64][LDH_F]
    __half* Vs = smh + 64 * LDH_F;               // [64][LDH_F]
    __half* Ps = smh + 2 * 64 * LDH_F;           // [128][LDH_F] (Q staging, then P)

    const int tid  = threadIdx.x;
    const int lane = tid & 31;
    const int wid  = tid >> 5;
    const int qc   = lane & 3;
    const int qg   = lane >> 2;
    const int h    = blockIdx.y;
    const int q0   = blockIdx.x * 128;
    const int colb = h * HD;

    const int g  = lane >> 3;
    const int l7 = lane & 7;
    // V B-frags (trans): matrix g -> rows k+((g&1)<<3)+l7, cols n+((g>>1)<<3)
    const uint32_t vs_addr = smem_u32(Vs) +
        (uint32_t)(((((g & 1) << 3) + l7) * LDH_F + ((g >> 1) << 3)) * 2);
    // K B-frags (non-trans): matrices (nt: m0,m1 = k-halves), (nt+1: m2,m3)
    // matrix j: rows nt*8 + ((j>>1)<<3) + l7, cols kc*16 + ((j&1)<<3)
    const uint32_t ks_addr = smem_u32(Ks) +
        (uint32_t)(((((g >> 1) << 3) + l7) * LDH_F + ((g & 1) << 3)) * 2);
    // P A-frags (non-trans): m0=a0 (rows+l7,c0), m1=a1 (rows+8+l7,c0),
    // m2=a2 (rows+l7,c8), m3=a3 (rows+8+l7,c8)
    const uint32_t ps_addr = smem_u32(Ps) +
        (uint32_t)(((((g & 1) << 3) + l7) * LDH_F + ((g >> 1) << 3)) * 2);

    // ---- Stage Q tile (pre-scaled, fp16): raw 16B copies into Ps ----
#pragma unroll
    for (int i = 0; i < 8; i++) {
        int id  = tid + i * 128;
        int row = id >> 3;
        int c8  = (id & 7) * 8;
        *(uint4*)(Ps + row * LDH_F + c8) =
            *(const uint4*)(qkv + (size_t)(q0 + row) * LDQKV + colb + c8);
    }
    __syncthreads();

    // ---- Q fragments to registers: 2 m-frags x 4 k16-chunks ----
    uint32_t qf[2][4][4];
#pragma unroll
    for (int mf = 0; mf < 2; mf++) {
        const int r0 = wid * 32 + mf * 16 + qg;
#pragma unroll
        for (int kc = 0; kc < 4; kc++) {
            const __half* qp = Ps + r0 * LDH_F + kc * 16 + 2 * qc;
            qf[mf][kc][0] = *(const uint32_t*)(qp);
            qf[mf][kc][1] = *(const uint32_t*)(qp + 8 * LDH_F);
            qf[mf][kc][2] = *(const uint32_t*)(qp + 8);
            qf[mf][kc][3] = *(const uint32_t*)(qp + 8 * LDH_F + 8);
        }
    }

    float o[2][8][4];
#pragma unroll
    for (int mf = 0; mf < 2; mf++)
#pragma unroll
        for (int nt = 0; nt < 8; nt++)
#pragma unroll
            for (int j = 0; j < 4; j++) o[mf][nt][j] = 0.0f;
    float m_run[2][2] = { {-CUDART_INF_F, -CUDART_INF_F},
                          {-CUDART_INF_F, -CUDART_INF_F} };
    float l_run[2][2] = { {0.f, 0.f}, {0.f, 0.f} };

    const int srow = tid >> 3;          // 0..15
    const int sc8  = (tid & 7) * 8;     // halves 0..56

    for (int k0 = 0; k0 < S_LEN; k0 += 64) {
        __syncthreads();   // prev tile reads done (covers Q-frag reads on t=0)
        // ---- Stage K, V tiles: raw LDG.128 -> STS.128 (L1-resident) ----
        {
            const __half* kb = qkv + (size_t)(k0 + srow) * LDQKV + colb + D_MODEL + sc8;
#pragma unroll
            for (int r = 0; r < 4; r++) {
                *(uint4*)(Ks + (srow + r * 16) * LDH_F + sc8) =
                    *(const uint4*)(kb + (size_t)(r * 16) * LDQKV);
                *(uint4*)(Vs + (srow + r * 16) * LDH_F + sc8) =
                    *(const uint4*)(kb + (size_t)(r * 16) * LDQKV + D_MODEL);
            }
        }
        __syncthreads();

        // ---- S = Q K^T, kc-outer: K B-frags via ldmatrix.x4, shared ----
        float s[2][8][4];
#pragma unroll
        for (int mf = 0; mf < 2; mf++)
#pragma unroll
            for (int nt = 0; nt < 8; nt++)
#pragma unroll
                for (int j = 0; j < 4; j++) s[mf][nt][j] = 0.0f;

#pragma unroll
        for (int kc = 0; kc < 4; kc++) {
            uint32_t bfr[8][2];
#pragma unroll
            for (int ntp = 0; ntp < 4; ntp++)
                ldsm_x4(bfr[2 * ntp][0], bfr[2 * ntp][1],
                        bfr[2 * ntp + 1][0], bfr[2 * ntp + 1][1],
                        ks_addr + (uint32_t)((ntp * 16 * LDH_F + kc * 16) * 2));
#pragma unroll
            for (int mf = 0; mf < 2; mf++)
#pragma unroll
                for (int nt = 0; nt < 8; nt++)
                    mma_f16(s[mf][nt], qf[mf][kc], bfr[nt], s[mf][nt]);
        }

        // ---- Online softmax per m-fragment (exp2 domain), store P (fp16) ----
#pragma unroll
        for (int mf = 0; mf < 2; mf++) {
            const int r0 = wid * 32 + mf * 16 + qg;
            const int r1 = r0 + 8;

            float mlo = -CUDART_INF_F, mhi = -CUDART_INF_F;
#pragma unroll
            for (int nt = 0; nt < 8; nt++) {
                mlo = fmaxf(mlo, fmaxf(s[mf][nt][0], s[mf][nt][1]));
                mhi = fmaxf(mhi, fmaxf(s[mf][nt][2], s[mf][nt][3]));
            }
            mlo = fmaxf(mlo, __shfl_xor_sync(0xffffffffu, mlo, 1));
            mlo = fmaxf(mlo, __shfl_xor_sync(0xffffffffu, mlo, 2));
            mhi = fmaxf(mhi, __shfl_xor_sync(0xffffffffu, mhi, 1));
            mhi = fmaxf(mhi, __shfl_xor_sync(0xffffffffu, mhi, 2));

            float mnlo = fmaxf(m_run[mf][0], mlo);
            float mnhi = fmaxf(m_run[mf][1], mhi);
            float alo  = ex2f(m_run[mf][0] - mnlo);   // 0 on first tile
            float ahi  = ex2f(m_run[mf][1] - mnhi);
            m_run[mf][0] = mnlo; m_run[mf][1] = mnhi;

            float tlo = 0.0f, thi = 0.0f;
#pragma unroll
            for (int nt = 0; nt < 8; nt++) {
                float p0 = ex2f(s[mf][nt][0] - mnlo);
                float p1 = ex2f(s[mf][nt][1] - mnlo);
                float p2 = ex2f(s[mf][nt][2] - mnhi);
                float p3 = ex2f(s[mf][nt][3] - mnhi);
                tlo += p0 + p1;
                thi += p2 + p3;
                *(__half2*)(Ps + r0 * LDH_F + nt * 8 + 2 * qc) = __floats2half2_rn(p0, p1);
                *(__half2*)(Ps + r1 * LDH_F + nt * 8 + 2 * qc) = __floats2half2_rn(p2, p3);
            }
            tlo += __shfl_xor_sync(0xffffffffu, tlo, 1);
            tlo += __shfl_xor_sync(0xffffffffu, tlo, 2);
            thi += __shfl_xor_sync(0xffffffffu, thi, 1);
            thi += __shfl_xor_sync(0xffffffffu, thi, 2);
            l_run[mf][0] = l_run[mf][0] * alo + tlo;
            l_run[mf][1] = l_run[mf][1] * ahi + thi;

#pragma unroll
            for (int nt = 0; nt < 8; nt++) {
                o[mf][nt][0] *= alo; o[mf][nt][1] *= alo;
                o[mf][nt][2] *= ahi; o[mf][nt][3] *= ahi;
            }
        }

        __syncwarp();   // P rows are warp-private; order STS before LDSM

        // ---- O += P V  (P A-frags + V B-frags via ldmatrix.x4) ----
#pragma unroll
        for (int kc = 0; kc < 4; kc++) {
            uint32_t vfr[8][2];
#pragma unroll
            for (int ntp = 0; ntp < 4; ntp++)
                ldsm_x4_t(vfr[2 * ntp][0], vfr[2 * ntp][1],
                          vfr[2 * ntp + 1][0], vfr[2 * ntp + 1][1],
                          vs_addr + (uint32_t)((kc * 16 * LDH_F + ntp * 16) * 2));
#pragma unroll
            for (int mf = 0; mf < 2; mf++) {
                uint32_t a[4];
                ldsm_x4(a[0], a[1], a[2], a[3],
                        ps_addr + (uint32_t)(((wid * 32 + mf * 16) * LDH_F + kc * 16) * 2));
#pragma unroll
                for (int nt = 0; nt < 8; nt++)
                    mma_f16(o[mf][nt], a, vfr[nt], o[mf][nt]);
            }
        }
    }

    // ---- Epilogue: normalize, store fp16 attn ----
#pragma unroll
    for (int mf = 0; mf < 2; mf++) {
        const int r0 = wid * 32 + mf * 16 + qg;
        const int r1 = r0 + 8;
        float ilo = 1.0f / l_run[mf][0];
        float ihi = 1.0f / l_run[mf][1];
#pragma unroll
        for (int nt = 0; nt < 8; nt++) {
            *(__half2*)(attn_out + (size_t)(q0 + r0) * D_MODEL + colb + nt * 8 + 2 * qc) =
                __floats2half2_rn(o[mf][nt][0] * ilo, o[mf][nt][1] * ilo);
            *(__half2*)(attn_out + (size_t)(q0 + r1) * D_MODEL + colb + nt * 8 + 2 * qc) =
                __floats2half2_rn(o[mf][nt][2] * ihi, o[mf][nt][3] * ihi);
        }
    }
}

// ---------------------------------------------------------------------------
// Launch: round-to-fp16 -> QKV proj -> flash -> out proj
// ---------------------------------------------------------------------------
extern "C" void kernel_launch(void* const* d_in, const int* in_sizes, int n_in,
                              void* d_out, int out_size)
{
    const float* query = (const float*)d_in[0];   // [1,4096,512]
    const float* w_in  = (const float*)d_in[1];   // [1536,512]
    const float* b_in  = (const float*)d_in[2];   // [1536]
    const float* w_out = (const float*)d_in[3];   // [512,512]
    const float* b_out = (const float*)d_in[4];   // [512]
    float*       out   = (float*)d_out;           // [1,4096,512]

    __half *qkv, *attn, *qr, *wi, *wo;
    cudaGetSymbolAddress((void**)&qkv,  g_qkv);
    cudaGetSymbolAddress((void**)&attn, g_attn);
    cudaGetSymbolAddress((void**)&qr,   g_qr);
    cudaGetSymbolAddress((void**)&wi,   g_wi);
    cudaGetSymbolAddress((void**)&wo,   g_wo);

    cudaFuncSetAttribute(gemm_f16_bias,
                         cudaFuncAttributeMaxDynamicSharedMemorySize, GEMM_SMEM);
    cudaFuncSetAttribute(flash_mma_kernel,
                         cudaFuncAttributeMaxDynamicSharedMemorySize, FLASH_SMEM);

    // 0) Round inputs to fp16
    {
        int nq = S_LEN * D_MODEL / 4;          // 524288
        int ni = 3 * D_MODEL * D_MODEL / 4;    // 196608
        int no = D_MODEL * D_MODEL / 4;        // 65536
        round_f16_kernel<<<(nq + 255) / 256, 256>>>(query, qr, nq);
        round_f16_kernel<<<(ni + 255) / 256, 256>>>(w_in,  wi, ni);
        round_f16_kernel<<<(no + 255) / 256, 256>>>(w_out, wo, no);
    }

    // 1) QKV projection (+ Q pre-scale incl. log2e; fp16 output)
    {
        dim3 grid(LDQKV / 128, S_LEN / 128);   // (12, 32)
        gemm_f16_bias<<<grid, 128, GEMM_SMEM>>>(qr, wi, b_in, qkv,
                                                S_LEN, LDQKV, D_MODEL, 1);
    }

    // 2) Flash attention per head (fp16 m16n8k16, full ldmatrix fragments)
    {
        dim3 grid(S_LEN / 128, H_NUM);   // (32, 8) = 256 CTAs
        flash_mma_kernel<<<grid, 128, FLASH_SMEM>>>(qkv, attn);
    }

    // 3) Output projection (fp32 output)
    {
        dim3 grid(D_MODEL / 128, S_LEN / 128);  // (4, 32)
        gemm_f16_bias<<<grid, 128, GEMM_SMEM>>>(attn, wo, b_out, out,
                                                S_LEN, D_MODEL, D_MODEL, 0);
    }
}